// round 1
// baseline (speedup 1.0000x reference)
#include <cuda_runtime.h>

// Problem shapes (fixed by the dataset):
//   inputs  : [16384, 512]  fp32   (d_in[0])
//   adj     : [16384,16384] fp32   (d_in[1])
//   weights : [512, 128]    fp32   (d_in[2])
//   out     : [16384, 128]  fp32
//
//   X = inputs @ weights      -> staged in __device__ scratch (8 MB, fits L2)
//   out = adj @ X             -> dominant GEMM (68.7 GFLOP)

#define M_DIM 16384
#define N_DIM 128
#define K1_DIM 512

// Scratch for intermediate X (no cudaMalloc allowed).
__device__ float g_X[M_DIM * N_DIM];

// ---------------------------------------------------------------------------
// Tiled SGEMM body: C[M,N] = A[M,K] @ B[K,N], N == 128 (one tile spans full N).
// Block tile 128x128, K-tile 8, 256 threads, 8x8 micro-tile per thread.
// Requires: M % 128 == 0, K % 8 == 0, N == 128, 16B-aligned rows.
// ---------------------------------------------------------------------------
__device__ __forceinline__ void sgemm_body(
    const float* __restrict__ A,
    const float* __restrict__ B,
    float* __restrict__ C,
    int K)
{
    constexpr int BM = 128;
    constexpr int BN = 128;
    constexpr int BK = 8;

    __shared__ float As[BK][BM];   // A tile, transposed: As[k][m]
    __shared__ float Bs[BK][BN];   // B tile: Bs[k][n]

    const int tid = threadIdx.x;          // 0..255
    const int tm  = tid >> 4;             // 0..15 -> row group
    const int tn  = tid & 15;             // 0..15 -> col group

    const int m0 = blockIdx.x * BM;

    // A-tile load mapping: each thread loads one float4 (128 rows x 8 k = 256 float4)
    const int a_row = tid >> 1;           // 0..127
    const int a_q   = (tid & 1) << 2;     // 0 or 4 (k offset)

    // B-tile load mapping: 8 rows x 128 cols = 256 float4
    const int b_row = tid >> 5;           // 0..7
    const int b_col = (tid & 31) << 2;    // 0,4,...,124

    float acc[8][8];
    #pragma unroll
    for (int i = 0; i < 8; i++)
        #pragma unroll
        for (int j = 0; j < 8; j++)
            acc[i][j] = 0.0f;

    const float* a_ptr = A + (long)(m0 + a_row) * K + a_q;
    const float* b_ptr = B + (long)b_row * N_DIM + b_col;

    for (int k0 = 0; k0 < K; k0 += BK) {
        // Load A tile (transpose into As[k][m])
        float4 av = *(const float4*)(a_ptr + k0);
        As[a_q + 0][a_row] = av.x;
        As[a_q + 1][a_row] = av.y;
        As[a_q + 2][a_row] = av.z;
        As[a_q + 3][a_row] = av.w;

        // Load B tile (coalesced)
        float4 bv = *(const float4*)(b_ptr + (long)k0 * N_DIM);
        *(float4*)&Bs[b_row][b_col] = bv;

        __syncthreads();

        #pragma unroll
        for (int kk = 0; kk < BK; kk++) {
            float a_frag[8], b_frag[8];
            *(float4*)(a_frag + 0) = *(const float4*)&As[kk][tm * 8 + 0];
            *(float4*)(a_frag + 4) = *(const float4*)&As[kk][tm * 8 + 4];
            *(float4*)(b_frag + 0) = *(const float4*)&Bs[kk][tn * 8 + 0];
            *(float4*)(b_frag + 4) = *(const float4*)&Bs[kk][tn * 8 + 4];

            #pragma unroll
            for (int i = 0; i < 8; i++)
                #pragma unroll
                for (int j = 0; j < 8; j++)
                    acc[i][j] = fmaf(a_frag[i], b_frag[j], acc[i][j]);
        }

        __syncthreads();
    }

    // Write back: each thread owns rows m0+tm*8..+7, cols tn*8..+7
    #pragma unroll
    for (int i = 0; i < 8; i++) {
        float* c_row = C + (long)(m0 + tm * 8 + i) * N_DIM + tn * 8;
        *(float4*)(c_row + 0) = make_float4(acc[i][0], acc[i][1], acc[i][2], acc[i][3]);
        *(float4*)(c_row + 4) = make_float4(acc[i][4], acc[i][5], acc[i][6], acc[i][7]);
    }
}

// GEMM1: X = inputs @ weights   (K = 512)
__global__ __launch_bounds__(256)
void gemm1_kernel(const float* __restrict__ inputs,
                  const float* __restrict__ weights)
{
    sgemm_body(inputs, weights, g_X, K1_DIM);
}

// GEMM2: out = adj @ X          (K = 16384)
__global__ __launch_bounds__(256)
void gemm2_kernel(const float* __restrict__ adj,
                  float* __restrict__ out)
{
    sgemm_body(adj, g_X, out, M_DIM);
}

extern "C" void kernel_launch(void* const* d_in, const int* in_sizes, int n_in,
                              void* d_out, int out_size)
{
    const float* inputs  = (const float*)d_in[0];   // [16384, 512]
    const float* adj     = (const float*)d_in[1];   // [16384, 16384]
    const float* weights = (const float*)d_in[2];   // [512, 128]
    float* out = (float*)d_out;                     // [16384, 128]

    dim3 grid(M_DIM / 128);
    dim3 block(256);

    gemm1_kernel<<<grid, block>>>(inputs, weights);
    gemm2_kernel<<<grid, block>>>(adj, out);
}

// round 3
// speedup vs baseline: 4.8793x; 4.8793x over previous
#include <cuda_runtime.h>
#include <cstdint>

// ---------------------------------------------------------------------------
// Shapes (fixed): inputs[16384,512] f32, adj[16384,16384] f32, W[512,128] f32
//   X   = inputs @ W        (2.1 GF)
//   out = adj @ X           (68.7 GF)
// Engine: mma.sync.aligned.m16n8k8.row.col.f32.tf32.tf32.f32 (sm_80+ feature,
// legal on the harness's sm_103 PTX target; tcgen05 is 103a-only and rejected).
// Numerics: W RN-rounded to tf32 (prepass); inputs/adj fed raw fp32 and
// HW-truncated to tf32. Both truncation biases compensated by scaling X once
// (GEMM2 linear in X):  SC = 1 + 2*0.72*2^-11.  X RN-rounded in epilogue.
// ---------------------------------------------------------------------------

#define M_DIM 16384
#define N_DIM 128
#define K1    512

__device__ float g_Wt[N_DIM * K1];              // W^T tf32-rounded [n][k]
__device__ float g_Xt[(long)N_DIM * M_DIM];     // X^T tf32-rounded [n][m] (8 MB)

#define BM 128
#define BN 128
#define BK 32
#define STAGES 3
#define LDS_F 36                                 // 32 + 4 skew (floats)
#define TILE_FLOATS (BM * LDS_F)                 // 4608
#define TILE_BYTES  (TILE_FLOATS * 4)            // 18432
#define SMEM_BYTES  (STAGES * 2 * TILE_BYTES)    // 110592

// ---------------- helpers ----------------
__device__ __forceinline__ uint32_t smem_u32(const void* p) {
    uint32_t a;
    asm("{ .reg .u64 t; cvta.to.shared.u64 t, %1; cvt.u32.u64 %0, t; }"
        : "=r"(a) : "l"(p));
    return a;
}
__device__ __forceinline__ float rna_tf32(float v) {
    uint32_t u;
    asm("cvt.rna.tf32.f32 %0, %1;" : "=r"(u) : "f"(v));
    return __uint_as_float(u);
}
#define CP_ASYNC16(dst, src) \
    asm volatile("cp.async.cg.shared.global [%0], [%1], 16;" :: "r"(dst), "l"(src) : "memory")
#define CP_COMMIT()  asm volatile("cp.async.commit_group;" ::: "memory")
#define CP_WAIT1()   asm volatile("cp.async.wait_group 1;" ::: "memory")
#define CP_WAIT0()   asm volatile("cp.async.wait_group 0;" ::: "memory")

__device__ __forceinline__ void mma_tf32(float c[4], const uint32_t a[4], const uint32_t b[2]) {
    asm volatile(
        "mma.sync.aligned.m16n8k8.row.col.f32.tf32.tf32.f32 "
        "{%0,%1,%2,%3}, {%4,%5,%6,%7}, {%8,%9}, {%0,%1,%2,%3};"
        : "+f"(c[0]), "+f"(c[1]), "+f"(c[2]), "+f"(c[3])
        : "r"(a[0]), "r"(a[1]), "r"(a[2]), "r"(a[3]), "r"(b[0]), "r"(b[1]));
}

// ---------------- pipeline pieces ----------------
// Load one BKx(BM|BN) stage: A rows [0,128) x 32 floats, B rows [0,128) x 32.
__device__ __forceinline__ void load_stage(
    uint32_t as_u32, uint32_t bs_u32,
    const float* __restrict__ A, long lda,
    const float* __restrict__ B, long ldb,
    int k0, int tid)
{
    #pragma unroll
    for (int j = 0; j < 4; j++) {
        int idx = tid + j * 256;              // 0..1023
        int row = idx >> 3;                   // 0..127
        int c4  = idx & 7;                    // 0..7 (float4 within row)
        uint32_t so = (uint32_t)(row * (LDS_F * 4) + c4 * 16);
        CP_ASYNC16(as_u32 + so, A + (long)row * lda + k0 + c4 * 4);
        CP_ASYNC16(bs_u32 + so, B + (long)row * ldb + k0 + c4 * 4);
    }
    CP_COMMIT();
}

// Compute one BK=32 stage: 4 k8-steps x 16 mma per warp.
__device__ __forceinline__ void compute_stage(
    const float* __restrict__ as, const float* __restrict__ bs,
    float acc[4][4][4], int wr, int wc, int gID, int tig)
{
    #pragma unroll
    for (int kk = 0; kk < 4; kk++) {
        const int col = kk * 8 + tig;
        uint32_t a[4][4], b[4][2];
        #pragma unroll
        for (int mt = 0; mt < 4; mt++) {
            int r0 = wr * 64 + mt * 16 + gID;
            a[mt][0] = __float_as_uint(as[r0 * LDS_F + col]);
            a[mt][1] = __float_as_uint(as[(r0 + 8) * LDS_F + col]);
            a[mt][2] = __float_as_uint(as[r0 * LDS_F + col + 4]);
            a[mt][3] = __float_as_uint(as[(r0 + 8) * LDS_F + col + 4]);
        }
        #pragma unroll
        for (int nt = 0; nt < 4; nt++) {
            int cn = wc * 32 + nt * 8 + gID;
            b[nt][0] = __float_as_uint(bs[cn * LDS_F + col]);
            b[nt][1] = __float_as_uint(bs[cn * LDS_F + col + 4]);
        }
        #pragma unroll
        for (int mt = 0; mt < 4; mt++)
            #pragma unroll
            for (int nt = 0; nt < 4; nt++)
                mma_tf32(acc[mt][nt], a[mt], b[nt]);
    }
}

template <int NITER>
__device__ __forceinline__ void gemm_mainloop(
    const float* __restrict__ A, long lda,     // A offset to CTA row 0
    const float* __restrict__ B, long ldb,     // B: [128 n][K] K-major
    float acc[4][4][4], float* smem)
{
    const int tid = threadIdx.x;
    const int wid = tid >> 5, lid = tid & 31;
    const int wr = wid >> 2, wc = wid & 3;
    const int gID = lid >> 2, tig = lid & 3;

    const uint32_t sbase = smem_u32(smem);

    #pragma unroll
    for (int mt = 0; mt < 4; mt++)
        #pragma unroll
        for (int nt = 0; nt < 4; nt++)
            #pragma unroll
            for (int r = 0; r < 4; r++) acc[mt][nt][r] = 0.0f;

    load_stage(sbase, sbase + STAGES * TILE_BYTES, A, lda, B, ldb, 0, tid);
    load_stage(sbase + TILE_BYTES, sbase + STAGES * TILE_BYTES + TILE_BYTES,
               A, lda, B, ldb, BK, tid);

    #pragma unroll 1
    for (int i = 0; i < NITER; i++) {
        if (i + 1 == NITER) { CP_WAIT0(); } else { CP_WAIT1(); }
        __syncthreads();
        if (i + 2 < NITER) {
            int s = (i + 2) % STAGES;
            load_stage(sbase + s * TILE_BYTES,
                       sbase + STAGES * TILE_BYTES + s * TILE_BYTES,
                       A, lda, B, ldb, (i + 2) * BK, tid);
        }
        int s = i % STAGES;
        compute_stage(smem + s * TILE_FLOATS,
                      smem + STAGES * TILE_FLOATS + s * TILE_FLOATS,
                      acc, wr, wc, gID, tig);
    }
}

// ---------------- prepass: W^T, RN-rounded ----------------
__global__ __launch_bounds__(256) void wt_kernel(const float* __restrict__ w) {
    int i = blockIdx.x * blockDim.x + threadIdx.x;   // over 65536 elems
    if (i < N_DIM * K1) {
        int n = i / K1, k = i % K1;
        g_Wt[i] = rna_tf32(w[(long)k * N_DIM + n]);
    }
}

// ---------------- GEMM1: Xt = ((inputs @ W) * SC)^T, RN-rounded -------------
__global__ __launch_bounds__(256, 1) void gemm1_kernel(const float* __restrict__ inputs) {
    extern __shared__ float smem[];
    float acc[4][4][4];
    const int m0 = blockIdx.x * BM;

    gemm_mainloop<K1 / BK>(inputs + (long)m0 * K1, K1, g_Wt, K1, acc, smem);

    // SC compensates tf32 truncation of inputs (GEMM1) and adj (GEMM2)
    const float SC = 1.00069f;
    const int wid = threadIdx.x >> 5, lid = threadIdx.x & 31;
    const int wr = wid >> 2, wc = wid & 3, gID = lid >> 2, tig = lid & 3;
    #pragma unroll
    for (int mt = 0; mt < 4; mt++)
        #pragma unroll
        for (int nt = 0; nt < 4; nt++) {
            int r = m0 + wr * 64 + mt * 16 + gID;
            int c = wc * 32 + nt * 8 + tig * 2;
            g_Xt[(long)c * M_DIM + r]           = rna_tf32(acc[mt][nt][0] * SC);
            g_Xt[(long)(c + 1) * M_DIM + r]     = rna_tf32(acc[mt][nt][1] * SC);
            g_Xt[(long)c * M_DIM + r + 8]       = rna_tf32(acc[mt][nt][2] * SC);
            g_Xt[(long)(c + 1) * M_DIM + r + 8] = rna_tf32(acc[mt][nt][3] * SC);
        }
}

// ---------------- GEMM2: out = adj @ X ----------------
__global__ __launch_bounds__(256, 1) void gemm2_kernel(const float* __restrict__ adj,
                                                       float* __restrict__ out) {
    extern __shared__ float smem[];
    float acc[4][4][4];
    const int m0 = blockIdx.x * BM;

    gemm_mainloop<M_DIM / BK>(adj + (long)m0 * M_DIM, M_DIM, g_Xt, M_DIM, acc, smem);

    const int wid = threadIdx.x >> 5, lid = threadIdx.x & 31;
    const int wr = wid >> 2, wc = wid & 3, gID = lid >> 2, tig = lid & 3;
    #pragma unroll
    for (int mt = 0; mt < 4; mt++)
        #pragma unroll
        for (int nt = 0; nt < 4; nt++) {
            long r = m0 + wr * 64 + mt * 16 + gID;
            int  c = wc * 32 + nt * 8 + tig * 2;
            *(float2*)&out[r * N_DIM + c]       = make_float2(acc[mt][nt][0], acc[mt][nt][1]);
            *(float2*)&out[(r + 8) * N_DIM + c] = make_float2(acc[mt][nt][2], acc[mt][nt][3]);
        }
}

// ---------------- launch ----------------
extern "C" void kernel_launch(void* const* d_in, const int* in_sizes, int n_in,
                              void* d_out, int out_size)
{
    const float* inputs  = (const float*)d_in[0];
    const float* adj     = (const float*)d_in[1];
    const float* weights = (const float*)d_in[2];
    float* out = (float*)d_out;

    cudaFuncSetAttribute(gemm1_kernel, cudaFuncAttributeMaxDynamicSharedMemorySize, SMEM_BYTES);
    cudaFuncSetAttribute(gemm2_kernel, cudaFuncAttributeMaxDynamicSharedMemorySize, SMEM_BYTES);

    wt_kernel<<<(N_DIM * K1 + 255) / 256, 256>>>(weights);
    gemm1_kernel<<<M_DIM / BM, 256, SMEM_BYTES>>>(inputs);
    gemm2_kernel<<<M_DIM / BM, 256, SMEM_BYTES>>>(adj, out);
}

// round 4
// speedup vs baseline: 5.0805x; 1.0412x over previous
#include <cuda_runtime.h>
#include <cstdint>

// ---------------------------------------------------------------------------
// Shapes (fixed): inputs[16384,512] f32, adj[16384,16384] f32, W[512,128] f32
//   X   = inputs @ W        (2.1 GF)
//   out = adj @ X           (68.7 GF)
// Engine: mma.sync.aligned.m16n8k8.row.col.f32.tf32.tf32.f32 (sm_103-legal).
// Fragments via ldmatrix.m8n8.x4.b16 (tf32: 8x8 b16 matrix == 8x4 tf32 tile,
// lane l -> element (l/4, l%4), matching the mma fragment layout exactly).
// Numerics: W RN-rounded to tf32; inputs/adj HW-truncated; both truncation
// biases folded into one scale on X.  rel_err ~4e-4 (validated R3).
// ---------------------------------------------------------------------------

#define M_DIM 16384
#define N_DIM 128
#define K1    512

__device__ float g_Wt[N_DIM * K1];              // W^T tf32-rounded [n][k]
__device__ float g_Xt[(long)N_DIM * M_DIM];     // X^T tf32-rounded [n][m] (8 MB)

#define BM 128
#define BN 128
#define BK 32
#define STAGES 3
#define LDS_F 36                                 // 32 + 4 skew (floats)
#define ROW_B (LDS_F * 4)                        // 144 bytes per tile row
#define TILE_FLOATS (BM * LDS_F)                 // 4608
#define TILE_BYTES  (TILE_FLOATS * 4)            // 18432
#define SMEM_BYTES  (STAGES * 2 * TILE_BYTES)    // 110592

// ---------------- helpers ----------------
__device__ __forceinline__ uint32_t smem_u32(const void* p) {
    uint32_t a;
    asm("{ .reg .u64 t; cvta.to.shared.u64 t, %1; cvt.u32.u64 %0, t; }"
        : "=r"(a) : "l"(p));
    return a;
}
__device__ __forceinline__ float rna_tf32(float v) {
    uint32_t u;
    asm("cvt.rna.tf32.f32 %0, %1;" : "=r"(u) : "f"(v));
    return __uint_as_float(u);
}
#define CP_ASYNC16(dst, src) \
    asm volatile("cp.async.cg.shared.global [%0], [%1], 16;" :: "r"(dst), "l"(src) : "memory")
#define CP_COMMIT()  asm volatile("cp.async.commit_group;" ::: "memory")
#define CP_WAIT1()   asm volatile("cp.async.wait_group 1;" ::: "memory")
#define CP_WAIT0()   asm volatile("cp.async.wait_group 0;" ::: "memory")

__device__ __forceinline__ void mma_tf32(float c[4], const uint32_t a[4], const uint32_t b[2]) {
    asm volatile(
        "mma.sync.aligned.m16n8k8.row.col.f32.tf32.tf32.f32 "
        "{%0,%1,%2,%3}, {%4,%5,%6,%7}, {%8,%9}, {%0,%1,%2,%3};"
        : "+f"(c[0]), "+f"(c[1]), "+f"(c[2]), "+f"(c[3])
        : "r"(a[0]), "r"(a[1]), "r"(a[2]), "r"(a[3]), "r"(b[0]), "r"(b[1]));
}
__device__ __forceinline__ void ldsm4(uint32_t r[4], uint32_t addr) {
    asm volatile("ldmatrix.sync.aligned.m8n8.x4.shared.b16 {%0,%1,%2,%3}, [%4];"
                 : "=r"(r[0]), "=r"(r[1]), "=r"(r[2]), "=r"(r[3]) : "r"(addr));
}

// ---------------- pipeline pieces ----------------
__device__ __forceinline__ void load_stage(
    uint32_t as_u32, uint32_t bs_u32,
    const float* __restrict__ A, long lda,
    const float* __restrict__ B, long ldb,
    int k0, int tid)
{
    #pragma unroll
    for (int j = 0; j < 4; j++) {
        int idx = tid + j * 256;              // 0..1023
        int row = idx >> 3;                   // 0..127
        int c4  = idx & 7;                    // 0..7 (float4 within row)
        uint32_t so = (uint32_t)(row * ROW_B + c4 * 16);
        CP_ASYNC16(as_u32 + so, A + (long)row * lda + k0 + c4 * 4);
        CP_ASYNC16(bs_u32 + so, B + (long)row * ldb + k0 + c4 * 4);
    }
    CP_COMMIT();
}

// Compute one BK=32 stage via ldmatrix fragments.
// aA/aB: per-lane base addresses inside this stage's A/B tiles.
// A matrices (x4, per mt,kk): m0=(rows+0,k0-3) m1=(rows+8,k0-3) m2=(+0,k4-7) m3=(+8,k4-7)
// B matrices (x4, per p,kk):  m0=b[2p][0] m1=b[2p][1] m2=b[2p+1][0] m3=b[2p+1][1]
__device__ __forceinline__ void compute_stage(
    uint32_t aA, uint32_t aB, float acc[4][4][4])
{
    #pragma unroll
    for (int kk = 0; kk < 4; kk++) {
        uint32_t a[4][4], b[2][4];
        #pragma unroll
        for (int mt = 0; mt < 4; mt++) ldsm4(a[mt], aA + mt * (16 * ROW_B) + kk * 32);
        #pragma unroll
        for (int p = 0; p < 2; p++)   ldsm4(b[p], aB + p * (16 * ROW_B) + kk * 32);
        #pragma unroll
        for (int mt = 0; mt < 4; mt++)
            #pragma unroll
            for (int nt = 0; nt < 4; nt++)
                mma_tf32(acc[mt][nt], a[mt], &b[nt >> 1][(nt & 1) * 2]);
    }
}

template <int NITER>
__device__ __forceinline__ void gemm_mainloop(
    const float* __restrict__ A, long lda,     // A offset to CTA row 0
    const float* __restrict__ B, long ldb,     // B: [128 n][K] K-major
    float acc[4][4][4], float* smem)
{
    const int tid = threadIdx.x;
    const int wid = tid >> 5, lid = tid & 31;
    const int wr = wid >> 2, wc = wid & 3;

    const uint32_t sbase = smem_u32(smem);

    // per-lane ldmatrix base offsets (bytes within a tile)
    //   A: row = wr*64 + (l&15)       [bit3 of l selects the +8-row matrix]
    //      col16 = (l>>4)&1           [second 16B = k cols 4..7]
    const uint32_t Abase = (uint32_t)((wr * 64 + (lid & 15)) * ROW_B + ((lid >> 4) & 1) * 16);
    //   B: row = wc*32 + ((l>>4)&1)*8 + (l&7)   [bit4 selects nt-odd rows]
    //      col16 = (l>>3)&1
    const uint32_t Bbase = (uint32_t)((wc * 32 + ((lid >> 4) & 1) * 8 + (lid & 7)) * ROW_B
                                      + ((lid >> 3) & 1) * 16);

    #pragma unroll
    for (int mt = 0; mt < 4; mt++)
        #pragma unroll
        for (int nt = 0; nt < 4; nt++)
            #pragma unroll
            for (int r = 0; r < 4; r++) acc[mt][nt][r] = 0.0f;

    load_stage(sbase, sbase + STAGES * TILE_BYTES, A, lda, B, ldb, 0, tid);
    load_stage(sbase + TILE_BYTES, sbase + STAGES * TILE_BYTES + TILE_BYTES,
               A, lda, B, ldb, BK, tid);

    #pragma unroll 1
    for (int i = 0; i < NITER; i++) {
        if (i + 1 == NITER) { CP_WAIT0(); } else { CP_WAIT1(); }
        __syncthreads();
        if (i + 2 < NITER) {
            int s = (i + 2) % STAGES;
            load_stage(sbase + s * TILE_BYTES,
                       sbase + STAGES * TILE_BYTES + s * TILE_BYTES,
                       A, lda, B, ldb, (i + 2) * BK, tid);
        }
        int s = i % STAGES;
        compute_stage(sbase + s * TILE_BYTES + Abase,
                      sbase + STAGES * TILE_BYTES + s * TILE_BYTES + Bbase,
                      acc);
    }
}

// ---------------- prepass: W^T, RN-rounded ----------------
__global__ __launch_bounds__(256) void wt_kernel(const float* __restrict__ w) {
    int i = blockIdx.x * blockDim.x + threadIdx.x;   // over 65536 elems
    if (i < N_DIM * K1) {
        int n = i / K1, k = i % K1;
        g_Wt[i] = rna_tf32(w[(long)k * N_DIM + n]);
    }
}

// ---------------- GEMM1: Xt = ((inputs @ W) * SC)^T, RN-rounded -------------
__global__ __launch_bounds__(256, 1) void gemm1_kernel(const float* __restrict__ inputs) {
    extern __shared__ float smem[];
    float acc[4][4][4];
    const int m0 = blockIdx.x * BM;

    gemm_mainloop<K1 / BK>(inputs + (long)m0 * K1, K1, g_Wt, K1, acc, smem);

    // SC compensates tf32 truncation of inputs (GEMM1) and adj (GEMM2)
    const float SC = 1.00069f;
    const int wid = threadIdx.x >> 5, lid = threadIdx.x & 31;
    const int wr = wid >> 2, wc = wid & 3, gID = lid >> 2, tig = lid & 3;
    #pragma unroll
    for (int mt = 0; mt < 4; mt++)
        #pragma unroll
        for (int nt = 0; nt < 4; nt++) {
            int r = m0 + wr * 64 + mt * 16 + gID;
            int c = wc * 32 + nt * 8 + tig * 2;
            g_Xt[(long)c * M_DIM + r]           = rna_tf32(acc[mt][nt][0] * SC);
            g_Xt[(long)(c + 1) * M_DIM + r]     = rna_tf32(acc[mt][nt][1] * SC);
            g_Xt[(long)c * M_DIM + r + 8]       = rna_tf32(acc[mt][nt][2] * SC);
            g_Xt[(long)(c + 1) * M_DIM + r + 8] = rna_tf32(acc[mt][nt][3] * SC);
        }
}

// ---------------- GEMM2: out = adj @ X ----------------
__global__ __launch_bounds__(256, 1) void gemm2_kernel(const float* __restrict__ adj,
                                                       float* __restrict__ out) {
    extern __shared__ float smem[];
    float acc[4][4][4];
    const int m0 = blockIdx.x * BM;

    gemm_mainloop<M_DIM / BK>(adj + (long)m0 * M_DIM, M_DIM, g_Xt, M_DIM, acc, smem);

    const int wid = threadIdx.x >> 5, lid = threadIdx.x & 31;
    const int wr = wid >> 2, wc = wid & 3, gID = lid >> 2, tig = lid & 3;
    #pragma unroll
    for (int mt = 0; mt < 4; mt++)
        #pragma unroll
        for (int nt = 0; nt < 4; nt++) {
            long r = m0 + wr * 64 + mt * 16 + gID;
            int  c = wc * 32 + nt * 8 + tig * 2;
            *(float2*)&out[r * N_DIM + c]       = make_float2(acc[mt][nt][0], acc[mt][nt][1]);
            *(float2*)&out[(r + 8) * N_DIM + c] = make_float2(acc[mt][nt][2], acc[mt][nt][3]);
        }
}

// ---------------- launch ----------------
extern "C" void kernel_launch(void* const* d_in, const int* in_sizes, int n_in,
                              void* d_out, int out_size)
{
    const float* inputs  = (const float*)d_in[0];
    const float* adj     = (const float*)d_in[1];
    const float* weights = (const float*)d_in[2];
    float* out = (float*)d_out;

    cudaFuncSetAttribute(gemm1_kernel, cudaFuncAttributeMaxDynamicSharedMemorySize, SMEM_BYTES);
    cudaFuncSetAttribute(gemm2_kernel, cudaFuncAttributeMaxDynamicSharedMemorySize, SMEM_BYTES);

    wt_kernel<<<(N_DIM * K1 + 255) / 256, 256>>>(weights);
    gemm1_kernel<<<M_DIM / BM, 256, SMEM_BYTES>>>(inputs);
    gemm2_kernel<<<M_DIM / BM, 256, SMEM_BYTES>>>(adj, out);
}

// round 5
// speedup vs baseline: 6.3093x; 1.2419x over previous
#include <cuda_runtime.h>
#include <cuda_fp16.h>
#include <cstdint>

// ---------------------------------------------------------------------------
// Shapes: inputs[16384,512] f32, adj[16384,16384] f32, W[512,128] f32
//   X   = inputs @ W   (2.1 GF)     out = adj @ X   (68.7 GF)
// Engine: mma.sync.aligned.m16n8k16.row.col.f32.f16.f16.f32 (2x tf32 rate).
// fp16 mantissa == tf32 mantissa (11 bit); all operands RN-rounded; fp32 accum.
// adj is converted f32->fp16 inline in GEMM2's producer (LDG->cvt->STS),
// register double-buffered one iteration ahead; X/inputs/W pre-converted.
// ---------------------------------------------------------------------------

#define M_DIM 16384
#define N_DIM 128
#define K1    512

__device__ __align__(16) __half g_inH[(long)M_DIM * K1];   // inputs fp16 (16 MB)
__device__ __align__(16) __half g_WtH[N_DIM * K1];         // W^T fp16 [n][k]
__device__ __align__(16) __half g_XtH[(long)N_DIM * M_DIM];// X^T fp16 [n][m] (4 MB)

#define BK 32
#define STAGES 3
#define ROW_B 80                                  // 64 B data + 16 B pad
#define TILE_B (128 * ROW_B)                      // 10240 B per tile
#define SMEM_BYTES (STAGES * 2 * TILE_B)          // 61440 B

// ---------------- helpers ----------------
__device__ __forceinline__ uint32_t smem_u32(const void* p) {
    uint32_t a;
    asm("{ .reg .u64 t; cvta.to.shared.u64 t, %1; cvt.u32.u64 %0, t; }"
        : "=r"(a) : "l"(p));
    return a;
}
#define CP_ASYNC16(dst, src) \
    asm volatile("cp.async.cg.shared.global [%0], [%1], 16;" :: "r"(dst), "l"(src) : "memory")
#define CP_COMMIT()  asm volatile("cp.async.commit_group;" ::: "memory")
#define CP_WAIT1()   asm volatile("cp.async.wait_group 1;" ::: "memory")
#define CP_WAIT0()   asm volatile("cp.async.wait_group 0;" ::: "memory")

__device__ __forceinline__ void mma_f16(float c[4], const uint32_t a[4], const uint32_t b[2]) {
    asm volatile(
        "mma.sync.aligned.m16n8k16.row.col.f32.f16.f16.f32 "
        "{%0,%1,%2,%3}, {%4,%5,%6,%7}, {%8,%9}, {%0,%1,%2,%3};"
        : "+f"(c[0]), "+f"(c[1]), "+f"(c[2]), "+f"(c[3])
        : "r"(a[0]), "r"(a[1]), "r"(a[2]), "r"(a[3]), "r"(b[0]), "r"(b[1]));
}
__device__ __forceinline__ void ldsm4(uint32_t r[4], uint32_t addr) {
    asm volatile("ldmatrix.sync.aligned.m8n8.x4.shared.b16 {%0,%1,%2,%3}, [%4];"
                 : "=r"(r[0]), "=r"(r[1]), "=r"(r[2]), "=r"(r[3]) : "r"(addr));
}
__device__ __forceinline__ uint32_t pack_h2(float x, float y) {
    __half2 h = __float22half2_rn(make_float2(x, y));
    return *(uint32_t*)&h;
}

// ---------------- producers ----------------
// fp16 tile via cp.async: 128 rows x 32 halves (64 B) -> 4 chunks/row.
__device__ __forceinline__ void load_f16_tile(
    uint32_t ts, const __half* __restrict__ T, long ldt, int k0, int tid)
{
    #pragma unroll
    for (int j = 0; j < 2; j++) {
        int idx = tid + j * 256;               // 0..511
        int row = idx >> 2, c = idx & 3;
        CP_ASYNC16(ts + (uint32_t)(row * ROW_B + c * 16),
                   T + (long)row * ldt + k0 + c * 8);
    }
}
// f32 A tile -> registers (16 floats per thread: row=tid>>1, half=tid&1)
__device__ __forceinline__ void ldg_A(float4 rb[4], const float* __restrict__ A,
                                      long lda, int k0, int tid)
{
    const float* p = A + (long)(tid >> 1) * lda + k0 + (tid & 1) * 16;
    rb[0] = *(const float4*)(p + 0);
    rb[1] = *(const float4*)(p + 4);
    rb[2] = *(const float4*)(p + 8);
    rb[3] = *(const float4*)(p + 12);
}
// convert + STS 16 halves (32 B) at row*80 + h*32
__device__ __forceinline__ void sts_A_cvt(uint32_t as, const float4 rb[4], int tid)
{
    uint32_t off = as + (uint32_t)((tid >> 1) * ROW_B + (tid & 1) * 32);
    uint32_t p0 = pack_h2(rb[0].x, rb[0].y), p1 = pack_h2(rb[0].z, rb[0].w);
    uint32_t p2 = pack_h2(rb[1].x, rb[1].y), p3 = pack_h2(rb[1].z, rb[1].w);
    uint32_t p4 = pack_h2(rb[2].x, rb[2].y), p5 = pack_h2(rb[2].z, rb[2].w);
    uint32_t p6 = pack_h2(rb[3].x, rb[3].y), p7 = pack_h2(rb[3].z, rb[3].w);
    asm volatile("st.shared.v4.b32 [%0], {%1,%2,%3,%4};"
                 :: "r"(off), "r"(p0), "r"(p1), "r"(p2), "r"(p3) : "memory");
    asm volatile("st.shared.v4.b32 [%0], {%1,%2,%3,%4};"
                 :: "r"(off + 16), "r"(p4), "r"(p5), "r"(p6), "r"(p7) : "memory");
}

// ---------------- compute: one BK=32 stage, m16n8k16 ----------------
__device__ __forceinline__ void compute_stage(uint32_t aA, uint32_t aB, float acc[4][4][4])
{
    #pragma unroll
    for (int kk = 0; kk < 2; kk++) {
        uint32_t a[4][4], b[2][4];
        #pragma unroll
        for (int mt = 0; mt < 4; mt++) ldsm4(a[mt], aA + mt * (16 * ROW_B) + kk * 32);
        #pragma unroll
        for (int p = 0; p < 2; p++)   ldsm4(b[p], aB + p * (16 * ROW_B) + kk * 32);
        #pragma unroll
        for (int mt = 0; mt < 4; mt++)
            #pragma unroll
            for (int nt = 0; nt < 4; nt++)
                mma_f16(acc[mt][nt], a[mt], &b[nt >> 1][(nt & 1) * 2]);
    }
}

// ---------------- main loop ----------------
// CONV=true : A is f32 (adj), converted inline.  CONV=false: A is fp16.
template <int NITER, bool CONV>
__device__ __forceinline__ void gemm_mainloop(
    const void* __restrict__ Av, long lda,
    const __half* __restrict__ B, long ldb,
    float acc[4][4][4], char* smem)
{
    const int tid = threadIdx.x;
    const int wid = tid >> 5, lid = tid & 31;
    const int wr = wid >> 2, wc = wid & 3;
    const uint32_t sbase = smem_u32(smem);

    const uint32_t Abase = (uint32_t)((wr * 64 + (lid & 15)) * ROW_B + ((lid >> 4) & 1) * 16);
    const uint32_t Bbase = (uint32_t)((wc * 32 + ((lid >> 4) & 1) * 8 + (lid & 7)) * ROW_B
                                      + ((lid >> 3) & 1) * 16);

    #pragma unroll
    for (int mt = 0; mt < 4; mt++)
        #pragma unroll
        for (int nt = 0; nt < 4; nt++)
            #pragma unroll
            for (int r = 0; r < 4; r++) acc[mt][nt][r] = 0.0f;

    const float*  Af = (const float*)Av;
    const __half* Ah = (const __half*)Av;
    float4 rb[4];

    // prologue: stages 0 and 1
    if (CONV) ldg_A(rb, Af, lda, 0, tid);
    else      load_f16_tile(sbase, Ah, lda, 0, tid);
    load_f16_tile(sbase + STAGES * TILE_B, B, ldb, 0, tid);
    CP_COMMIT();
    if (CONV) { sts_A_cvt(sbase, rb, tid); ldg_A(rb, Af, lda, BK, tid); }
    else      load_f16_tile(sbase + TILE_B, Ah, lda, BK, tid);
    load_f16_tile(sbase + STAGES * TILE_B + TILE_B, B, ldb, BK, tid);
    CP_COMMIT();
    CP_WAIT1();
    __syncthreads();

    #pragma unroll 1
    for (int i = 0; i < NITER; i++) {
        if (CONV && (i + 1 < NITER))
            sts_A_cvt(sbase + ((i + 1) % STAGES) * TILE_B, rb, tid);
        if (i + 2 < NITER) {
            int s = (i + 2) % STAGES;
            if (CONV) ldg_A(rb, Af, lda, (i + 2) * BK, tid);
            else      load_f16_tile(sbase + s * TILE_B, Ah, lda, (i + 2) * BK, tid);
            load_f16_tile(sbase + STAGES * TILE_B + s * TILE_B, B, ldb, (i + 2) * BK, tid);
            CP_COMMIT();
        }
        int s = i % STAGES;
        compute_stage(sbase + s * TILE_B + Abase,
                      sbase + STAGES * TILE_B + s * TILE_B + Bbase, acc);
        if (i + 2 < NITER) { CP_WAIT1(); } else { CP_WAIT0(); }
        __syncthreads();
    }
}

// ---------------- prepasses ----------------
__global__ __launch_bounds__(256) void cvt_inputs_kernel(const float* __restrict__ in) {
    const long n4 = (long)M_DIM * K1 / 4;
    for (long i = blockIdx.x * blockDim.x + threadIdx.x; i < n4;
         i += (long)gridDim.x * blockDim.x) {
        float4 v = ((const float4*)in)[i];
        uint2 o;
        o.x = pack_h2(v.x, v.y);
        o.y = pack_h2(v.z, v.w);
        ((uint2*)g_inH)[i] = o;
    }
}
__global__ __launch_bounds__(256) void wt_kernel(const float* __restrict__ w) {
    int i = blockIdx.x * blockDim.x + threadIdx.x;
    if (i < N_DIM * K1) {
        int n = i / K1, k = i % K1;
        g_WtH[i] = __float2half_rn(w[(long)k * N_DIM + n]);
    }
}

// ---------------- GEMM1: XtH = (inputs @ W)^T fp16 ----------------
__global__ __launch_bounds__(256, 1) void gemm1_kernel() {
    extern __shared__ char smem[];
    float acc[4][4][4];
    const int m0 = blockIdx.x * 128;

    gemm_mainloop<K1 / BK, false>(g_inH + (long)m0 * K1, K1, g_WtH, K1, acc, smem);

    const int wid = threadIdx.x >> 5, lid = threadIdx.x & 31;
    const int wr = wid >> 2, wc = wid & 3, gID = lid >> 2, tig = lid & 3;
    #pragma unroll
    for (int mt = 0; mt < 4; mt++)
        #pragma unroll
        for (int nt = 0; nt < 4; nt++) {
            int r = m0 + wr * 64 + mt * 16 + gID;
            int c = wc * 32 + nt * 8 + tig * 2;
            g_XtH[(long)c * M_DIM + r]           = __float2half_rn(acc[mt][nt][0]);
            g_XtH[(long)(c + 1) * M_DIM + r]     = __float2half_rn(acc[mt][nt][1]);
            g_XtH[(long)c * M_DIM + r + 8]       = __float2half_rn(acc[mt][nt][2]);
            g_XtH[(long)(c + 1) * M_DIM + r + 8] = __float2half_rn(acc[mt][nt][3]);
        }
}

// ---------------- GEMM2: out = adj @ X ----------------
__global__ __launch_bounds__(256, 1) void gemm2_kernel(const float* __restrict__ adj,
                                                       float* __restrict__ out) {
    extern __shared__ char smem[];
    float acc[4][4][4];
    const int m0 = blockIdx.x * 128;

    gemm_mainloop<M_DIM / BK, true>(adj + (long)m0 * M_DIM, M_DIM, g_XtH, M_DIM, acc, smem);

    const int wid = threadIdx.x >> 5, lid = threadIdx.x & 31;
    const int wr = wid >> 2, wc = wid & 3, gID = lid >> 2, tig = lid & 3;
    #pragma unroll
    for (int mt = 0; mt < 4; mt++)
        #pragma unroll
        for (int nt = 0; nt < 4; nt++) {
            long r = m0 + wr * 64 + mt * 16 + gID;
            int  c = wc * 32 + nt * 8 + tig * 2;
            *(float2*)&out[r * N_DIM + c]       = make_float2(acc[mt][nt][0], acc[mt][nt][1]);
            *(float2*)&out[(r + 8) * N_DIM + c] = make_float2(acc[mt][nt][2], acc[mt][nt][3]);
        }
}

// ---------------- launch ----------------
extern "C" void kernel_launch(void* const* d_in, const int* in_sizes, int n_in,
                              void* d_out, int out_size)
{
    const float* inputs  = (const float*)d_in[0];
    const float* adj     = (const float*)d_in[1];
    const float* weights = (const float*)d_in[2];
    float* out = (float*)d_out;

    cudaFuncSetAttribute(gemm1_kernel, cudaFuncAttributeMaxDynamicSharedMemorySize, SMEM_BYTES);
    cudaFuncSetAttribute(gemm2_kernel, cudaFuncAttributeMaxDynamicSharedMemorySize, SMEM_BYTES);

    cvt_inputs_kernel<<<1024, 256>>>(inputs);
    wt_kernel<<<(N_DIM * K1 + 255) / 256, 256>>>(weights);
    gemm1_kernel<<<M_DIM / 128, 256, SMEM_BYTES>>>();
    gemm2_kernel<<<M_DIM / 128, 256, SMEM_BYTES>>>(adj, out);
}